// round 16
// baseline (speedup 1.0000x reference)
#include <cuda_runtime.h>
#include <cuda_fp16.h>
#include <cstdint>

// Problem constants
#define N_TOK   4096
#define C_BOOKS 128
#define K_CENT  16
#define V_LEN   16
#define IN_DIM  2048
#define OUT_DIM 4096
#define KTOT    2048                   // 128 books * 16 centroids (one-hot K)

// Scratch (allocation-free rule: device globals)
__device__ unsigned char g_idxT[(size_t)C_BOOKS * N_TOK];   // [c][token]
__device__ __half g_Bt[(size_t)OUT_DIM * KTOT];             // [o][k] k-contiguous, 16 MB

// ---------------------------------------------------------------------------
__device__ __forceinline__ uint32_t smem_u32(const void* p) {
    uint32_t a;
    asm("{ .reg .u64 t; cvta.to.shared.u64 t, %1; cvt.u32.u64 %0, t; }" : "=r"(a) : "l"(p));
    return a;
}
// oh(t) = 0x3C00 if t==0, 0x3C000000 if t==1, else 0  ==  low32(0x3C00 << (16t)).
// PTX shl.b64 clamps shift >= 64 to produce 0 (t in 0..15 -> s in 0..240).
__device__ __forceinline__ uint32_t shl_oh(uint32_t s) {
    uint64_t r;
    asm("shl.b64 %0, 15360, %1;" : "=l"(r) : "r"(s));   // 15360 = 0x3C00
    return (uint32_t)r;
}

// ---------------------------------------------------------------------------
// Fused prologue: blocks [0, 512) = quant (Chebyshev argmin, exact) -> g_idxT;
// blocks [512, 2560) = build fp16 LUT matrix B.
// quant inner loop uses a split fmax tree (d0/d1) for shorter dep chains;
// fmax is associative on finite data -> indices bit-identical.
// ---------------------------------------------------------------------------
__global__ void __launch_bounds__(256) prologue_kernel(
    const float* __restrict__ x, const float* __restrict__ wgt,
    const float* __restrict__ cents)
{
    __shared__ float sc[32 * 256];
    int tid = threadIdx.x;

    if (blockIdx.x < 512) {
        int blk  = blockIdx.x;
        int lane = tid & 31, w = tid >> 5;
        int token = (blk & 127) * 32 + lane;
        int cbase = (blk >> 7) * 32;

        for (int i = tid; i < 32 * 256; i += 256)
            sc[i] = cents[(size_t)cbase * 256 + i];
        __syncthreads();

        const float* xrow = x + (size_t)token * IN_DIM;
        for (int cl = w * 4; cl < w * 4 + 4; ++cl) {
            int c = cbase + cl;
            float xv[16];
            const float4* xp = (const float4*)(xrow + c * V_LEN);
#pragma unroll
            for (int q = 0; q < 4; ++q) {
                float4 t = xp[q];
                xv[q*4+0] = t.x; xv[q*4+1] = t.y; xv[q*4+2] = t.z; xv[q*4+3] = t.w;
            }
            const float4* cb = (const float4*)(sc + cl * 256);
            float best = 3.4028235e38f; int bi = 0;
#pragma unroll
            for (int k = 0; k < K_CENT; ++k) {
                float d0 = 0.0f, d1 = 0.0f;
#pragma unroll
                for (int q = 0; q < 2; ++q) {
                    float4 t = cb[k * 4 + q];
                    d0 = fmaxf(d0, fabsf(xv[q*4+0] - t.x));
                    d0 = fmaxf(d0, fabsf(xv[q*4+1] - t.y));
                    d0 = fmaxf(d0, fabsf(xv[q*4+2] - t.z));
                    d0 = fmaxf(d0, fabsf(xv[q*4+3] - t.w));
                }
#pragma unroll
                for (int q = 2; q < 4; ++q) {
                    float4 t = cb[k * 4 + q];
                    d1 = fmaxf(d1, fabsf(xv[q*4+0] - t.x));
                    d1 = fmaxf(d1, fabsf(xv[q*4+1] - t.y));
                    d1 = fmaxf(d1, fabsf(xv[q*4+2] - t.z));
                    d1 = fmaxf(d1, fabsf(xv[q*4+3] - t.w));
                }
                float d = fmaxf(d0, d1);
                if (d < best) { best = d; bi = k; }   // strict < == first min (argmin)
            }
            g_idxT[(size_t)c * N_TOK + token] = (unsigned char)bi;
        }
    } else {
        int blk = blockIdx.x - 512;               // 0..2047
        int c   = blk & 127;
        int o   = (blk >> 7) * 256 + tid;
        sc[tid] = cents[(size_t)c * 256 + tid];
        __syncthreads();

        float acc[K_CENT];
#pragma unroll
        for (int k = 0; k < K_CENT; ++k) acc[k] = 0.0f;
#pragma unroll
        for (int v = 0; v < V_LEN; ++v) {
            float wv = wgt[(size_t)(c * V_LEN + v) * OUT_DIM + o];
#pragma unroll
            for (int k = 0; k < K_CENT; ++k)
                acc[k] = fmaf(sc[k * V_LEN + v], wv, acc[k]);
        }
        __half2 h[8];
#pragma unroll
        for (int j = 0; j < 8; ++j)
            h[j] = __floats2half2_rn(acc[2 * j], acc[2 * j + 1]);
        uint4* dst = (uint4*)(g_Bt + (size_t)o * KTOT + c * 16);
        dst[0] = *(uint4*)&h[0];
        dst[1] = *(uint4*)&h[4];
    }
}

// ---------------------------------------------------------------------------
// Dense one-hot GEMM — R14 group-barrier structure with:
//  * 3-stage B ring, ONE group barrier per chunk (write target (s+2)%3 was
//    consumed at iter s-1, ordered by this iter's barrier)
//  * permuted idx staging: each thread's 4 row-bytes land in ONE u32
//  * shift-LUT one-hot synthesis (shl.b64, no ISETP/SEL chains)
// ---------------------------------------------------------------------------
#define SM_IDX  0                       // 128 books x 128 tokens = 16 KB (permuted)
#define BSTG    (128 * 144)             // 18432 B per stage
#define SM_B    16384
#define SM_BIAS (SM_B + 3 * BSTG)       // 71680
#define SM_TOT  (SM_BIAS + 512)         // 72192

#define MMA(d, a0, a1, a2, a3, b0, b1) \
    asm volatile("mma.sync.aligned.m16n8k16.row.col.f32.f16.f16.f32 " \
        "{%0,%1,%2,%3}, {%4,%5,%6,%7}, {%8,%9}, {%0,%1,%2,%3};" \
        : "+f"((d)[0]), "+f"((d)[1]), "+f"((d)[2]), "+f"((d)[3]) \
        : "r"(a0), "r"(a1), "r"(a2), "r"(a3), "r"(b0), "r"(b1))

#define GBAR(id) asm volatile("bar.sync %0, 128;" :: "r"(id) : "memory")

__global__ void __launch_bounds__(256, 2) onehot_hmma_kernel(
    const float* __restrict__ bias, float* __restrict__ out)
{
    extern __shared__ __align__(128) unsigned char smem[];
    const uint32_t sb = smem_u32(smem);
    const int tid = threadIdx.x, lane = tid & 31, w = tid >> 5;
    const int ms = w & 3, ns = w >> 2;          // 4 m-strips x 2 n-strips
    const int gtid = tid & 127;                 // thread id within n-half group
    const int gbar = 1 + ns;                    // named barrier per group
    const int m0 = blockIdx.y * 128, o0 = blockIdx.x * 128;

    const __half* gB = g_Bt + (size_t)o0 * KTOT;

    // Prologue cp.async: each group loads ITS 64 B-rows for stages 0, 1
#pragma unroll
    for (int s = 0; s < 2; ++s) {
        uint32_t dst = sb + SM_B + s * BSTG;
        const __half* src = gB + s * 64;
#pragma unroll
        for (int r = 0; r < 4; ++r) {
            int i = gtid + r * 128, n = ns * 64 + (i >> 3), ch = i & 7;
            asm volatile("cp.async.cg.shared.global [%0], [%1], 16;"
                :: "r"(dst + n * 144 + ch * 16), "l"(src + (size_t)n * KTOT + ch * 8));
        }
        asm volatile("cp.async.commit_group;" ::: "memory");
    }

    // Stage idx PERMUTED: byte for local token t of book c goes to
    //   s_idx[c*128 + (t>>5)*32 + (t&7)*4 + ((t&31)>>3)]
    // so thread (ms, g=lane>>2) later loads its 4 rows {g, g+8, g+16, g+24}
    // of strip ms as ONE aligned u32.
    {
        unsigned char* si = smem + SM_IDX;
        for (int i = tid; i < 1024; i += 256) {
            int c = i >> 3, t0 = (i & 7) * 16;
            uint4 v = *(const uint4*)(g_idxT + ((size_t)c << 12) + m0 + t0);
            const unsigned char* vb = (const unsigned char*)&v;
            int strip = t0 >> 5;                 // each 16-token group is within one strip
#pragma unroll
            for (int j = 0; j < 16; ++j) {
                int tw = (t0 & 31) + j;          // within-strip index 0..31
                si[c * 128 + strip * 32 + (tw & 7) * 4 + (tw >> 3)] = vb[j];
            }
        }
        float* sbias = (float*)(smem + SM_BIAS);
        if (tid < 128) sbias[tid] = bias[o0 + tid];
    }
    __syncthreads();

    float acc[2][8][4];
#pragma unroll
    for (int mf = 0; mf < 2; ++mf)
#pragma unroll
        for (int nf = 0; nf < 8; ++nf)
#pragma unroll
            for (int q = 0; q < 4; ++q) acc[mf][nf][q] = 0.0f;

    const uint32_t c0    = (uint32_t)((lane & 3) * 2);
    const uint32_t xmask = c0 * 0x01010101u;
    const uint32_t lmb   = (uint32_t)((lane & 7) * 144 + (lane >> 3) * 16);
    const unsigned char* s_idx = smem + SM_IDX;
    const uint32_t ioff  = (uint32_t)(ms * 32 + (lane >> 2) * 4);

    for (int s = 0; s < 32; ++s) {
        asm volatile("cp.async.wait_group 1;" ::: "memory");
        GBAR(gbar);   // group's half of stage s ready; iter s-1 reads complete
        uint32_t bufB = sb + SM_B + (s % 3) * BSTG;
#pragma unroll
        for (int cb = 0; cb < 4; ++cb) {
            int c = s * 4 + cb;
            uint32_t p  = *(const uint32_t*)(s_idx + (c << 7) + ioff);
            uint32_t tp = p ^ xmask;             // bytes = t for rows g, g+8, g+16, g+24
            uint32_t s0 = (tp & 0xFu) << 4;
            uint32_t s1 = ((tp >> 8) & 0xFu) << 4;
            uint32_t s2 = ((tp >> 16) & 0xFu) << 4;
            uint32_t s3 = (tp >> 24) << 4;
            uint32_t a00 = shl_oh(s0),        a01 = shl_oh(s1);
            uint32_t a02 = shl_oh(s0 ^ 128u), a03 = shl_oh(s1 ^ 128u);
            uint32_t a10 = shl_oh(s2),        a11 = shl_oh(s3);
            uint32_t a12 = shl_oh(s2 ^ 128u), a13 = shl_oh(s3 ^ 128u);
            uint32_t kb = bufB + (uint32_t)(cb * 32) + (uint32_t)(ns * 64 * 144) + lmb;
#pragma unroll
            for (int nf = 0; nf < 8; ++nf) {
                uint32_t b0, b1;
                asm volatile("ldmatrix.sync.aligned.m8n8.x2.shared.b16 {%0,%1}, [%2];"
                             : "=r"(b0), "=r"(b1) : "r"(kb + (uint32_t)(nf * 8 * 144)));
                MMA(acc[0][nf], a00, a01, a02, a03, b0, b1);
                MMA(acc[1][nf], a10, a11, a12, a13, b0, b1);
            }
        }
        // Issue stage s+2 into ring slot (s+2)%3 == (s-1)%3 (consumed at s-1,
        // ordered by this iteration's GBAR). No second barrier needed.
        if (s + 2 < 32) {
            uint32_t dst = sb + SM_B + ((s + 2) % 3) * BSTG;
            const __half* src = gB + (s + 2) * 64;
#pragma unroll
            for (int r = 0; r < 4; ++r) {
                int i = gtid + r * 128, n = ns * 64 + (i >> 3), ch = i & 7;
                asm volatile("cp.async.cg.shared.global [%0], [%1], 16;"
                    :: "r"(dst + n * 144 + ch * 16), "l"(src + (size_t)n * KTOT + ch * 8));
            }
        }
        asm volatile("cp.async.commit_group;" ::: "memory");
    }

    // Epilogue: add bias, store
    const float* sbias = (const float*)(smem + SM_BIAS);
#pragma unroll
    for (int mf = 0; mf < 2; ++mf) {
        int row = m0 + ms * 32 + mf * 16 + (lane >> 2);
#pragma unroll
        for (int nf = 0; nf < 8; ++nf) {
            int colL = ns * 64 + nf * 8 + (int)c0;
            float2 bv = *(const float2*)(sbias + colL);
            float2 v0 = make_float2(acc[mf][nf][0] + bv.x, acc[mf][nf][1] + bv.y);
            float2 v1 = make_float2(acc[mf][nf][2] + bv.x, acc[mf][nf][3] + bv.y);
            *(float2*)(out + (size_t)row * OUT_DIM + o0 + colL) = v0;
            *(float2*)(out + (size_t)(row + 8) * OUT_DIM + o0 + colL) = v1;
        }
    }
}

// ---------------------------------------------------------------------------
extern "C" void kernel_launch(void* const* d_in, const int* in_sizes, int n_in,
                              void* d_out, int out_size)
{
    const float* x     = (const float*)d_in[0];
    const float* wgt   = (const float*)d_in[1];
    const float* cents = (const float*)d_in[2];
    const float* bias  = (const float*)d_in[3];
    float*       out   = (float*)d_out;

    cudaFuncSetAttribute(onehot_hmma_kernel,
                         cudaFuncAttributeMaxDynamicSharedMemorySize, SM_TOT);

    prologue_kernel<<<2560, 256>>>(x, wgt, cents);
    onehot_hmma_kernel<<<dim3(OUT_DIM / 128, N_TOK / 128), 256, SM_TOT>>>(bias, out);
}

// round 17
// speedup vs baseline: 1.0064x; 1.0064x over previous
#include <cuda_runtime.h>
#include <cuda_fp16.h>
#include <cstdint>

// Problem constants
#define N_TOK   4096
#define C_BOOKS 128
#define K_CENT  16
#define V_LEN   16
#define IN_DIM  2048
#define OUT_DIM 4096
#define KTOT    2048                   // 128 books * 16 centroids (one-hot K)

// Scratch (allocation-free rule: device globals)
__device__ unsigned char g_idxT[(size_t)C_BOOKS * N_TOK];   // [c][token]
__device__ __half g_Bt[(size_t)OUT_DIM * KTOT];             // [o][k] k-contiguous, 16 MB

// ---------------------------------------------------------------------------
__device__ __forceinline__ uint32_t smem_u32(const void* p) {
    uint32_t a;
    asm("{ .reg .u64 t; cvta.to.shared.u64 t, %1; cvt.u32.u64 %0, t; }" : "=r"(a) : "l"(p));
    return a;
}
// oh(t) = 0x3C00 if t==0, 0x3C000000 if t==1, else 0  ==  low32(0x3C00 << (16t)).
// PTX shl.b64 clamps shift >= 64 to produce 0 (t in 0..15 -> s in 0..240).
__device__ __forceinline__ uint32_t shl_oh(uint32_t s) {
    uint64_t r;
    asm("shl.b64 %0, 15360, %1;" : "=l"(r) : "r"(s));   // 15360 = 0x3C00
    return (uint32_t)r;
}

// ---------------------------------------------------------------------------
// Fused prologue (exact R10 version, known 31us total):
// blocks [0, 512) = quant (Chebyshev argmin, exact) -> g_idxT;
// blocks [512, 2560) = build fp16 LUT matrix B.
// ---------------------------------------------------------------------------
__global__ void __launch_bounds__(256) prologue_kernel(
    const float* __restrict__ x, const float* __restrict__ wgt,
    const float* __restrict__ cents)
{
    __shared__ float sc[32 * 256];
    int tid = threadIdx.x;

    if (blockIdx.x < 512) {
        int blk  = blockIdx.x;
        int lane = tid & 31, w = tid >> 5;
        int token = (blk & 127) * 32 + lane;
        int cbase = (blk >> 7) * 32;

        for (int i = tid; i < 32 * 256; i += 256)
            sc[i] = cents[(size_t)cbase * 256 + i];
        __syncthreads();

        const float* xrow = x + (size_t)token * IN_DIM;
        for (int cl = w * 4; cl < w * 4 + 4; ++cl) {
            int c = cbase + cl;
            float xv[16];
            const float4* xp = (const float4*)(xrow + c * V_LEN);
#pragma unroll
            for (int q = 0; q < 4; ++q) {
                float4 t = xp[q];
                xv[q*4+0] = t.x; xv[q*4+1] = t.y; xv[q*4+2] = t.z; xv[q*4+3] = t.w;
            }
            const float4* cb = (const float4*)(sc + cl * 256);
            float best = 3.4028235e38f; int bi = 0;
#pragma unroll
            for (int k = 0; k < K_CENT; ++k) {
                float d = 0.0f;
#pragma unroll
                for (int q = 0; q < 4; ++q) {
                    float4 t = cb[k * 4 + q];
                    d = fmaxf(d, fabsf(xv[q*4+0] - t.x));
                    d = fmaxf(d, fabsf(xv[q*4+1] - t.y));
                    d = fmaxf(d, fabsf(xv[q*4+2] - t.z));
                    d = fmaxf(d, fabsf(xv[q*4+3] - t.w));
                }
                if (d < best) { best = d; bi = k; }   // strict < == first min (argmin)
            }
            g_idxT[(size_t)c * N_TOK + token] = (unsigned char)bi;
        }
    } else {
        int blk = blockIdx.x - 512;               // 0..2047
        int c   = blk & 127;
        int o   = (blk >> 7) * 256 + tid;
        sc[tid] = cents[(size_t)c * 256 + tid];
        __syncthreads();

        float acc[K_CENT];
#pragma unroll
        for (int k = 0; k < K_CENT; ++k) acc[k] = 0.0f;
#pragma unroll
        for (int v = 0; v < V_LEN; ++v) {
            float wv = wgt[(size_t)(c * V_LEN + v) * OUT_DIM + o];
#pragma unroll
            for (int k = 0; k < K_CENT; ++k)
                acc[k] = fmaf(sc[k * V_LEN + v], wv, acc[k]);
        }
        __half2 h[8];
#pragma unroll
        for (int j = 0; j < 8; ++j)
            h[j] = __floats2half2_rn(acc[2 * j], acc[2 * j + 1]);
        uint4* dst = (uint4*)(g_Bt + (size_t)o * KTOT + c * 16);
        dst[0] = *(uint4*)&h[0];
        dst[1] = *(uint4*)&h[4];
    }
}

// ---------------------------------------------------------------------------
// Dense one-hot GEMM — exact R16 version (best measured: 172.6us):
//  * group-scoped barriers (each 128-thread n-half owns its B rows)
//  * 3-stage B ring, ONE group barrier per chunk
//  * permuted idx staging (4 row-bytes per thread = one u32 load)
//  * shift-LUT one-hot synthesis (shl.b64)
// ---------------------------------------------------------------------------
#define SM_IDX  0                       // 128 books x 128 tokens = 16 KB (permuted)
#define BSTG    (128 * 144)             // 18432 B per stage
#define SM_B    16384
#define SM_BIAS (SM_B + 3 * BSTG)       // 71680
#define SM_TOT  (SM_BIAS + 512)         // 72192

#define MMA(d, a0, a1, a2, a3, b0, b1) \
    asm volatile("mma.sync.aligned.m16n8k16.row.col.f32.f16.f16.f32 " \
        "{%0,%1,%2,%3}, {%4,%5,%6,%7}, {%8,%9}, {%0,%1,%2,%3};" \
        : "+f"((d)[0]), "+f"((d)[1]), "+f"((d)[2]), "+f"((d)[3]) \
        : "r"(a0), "r"(a1), "r"(a2), "r"(a3), "r"(b0), "r"(b1))

#define GBAR(id) asm volatile("bar.sync %0, 128;" :: "r"(id) : "memory")

__global__ void __launch_bounds__(256, 2) onehot_hmma_kernel(
    const float* __restrict__ bias, float* __restrict__ out)
{
    extern __shared__ __align__(128) unsigned char smem[];
    const uint32_t sb = smem_u32(smem);
    const int tid = threadIdx.x, lane = tid & 31, w = tid >> 5;
    const int ms = w & 3, ns = w >> 2;          // 4 m-strips x 2 n-strips
    const int gtid = tid & 127;                 // thread id within n-half group
    const int gbar = 1 + ns;                    // named barrier per group
    const int m0 = blockIdx.y * 128, o0 = blockIdx.x * 128;

    const __half* gB = g_Bt + (size_t)o0 * KTOT;

    // Prologue cp.async: each group loads ITS 64 B-rows for stages 0, 1
#pragma unroll
    for (int s = 0; s < 2; ++s) {
        uint32_t dst = sb + SM_B + s * BSTG;
        const __half* src = gB + s * 64;
#pragma unroll
        for (int r = 0; r < 4; ++r) {
            int i = gtid + r * 128, n = ns * 64 + (i >> 3), ch = i & 7;
            asm volatile("cp.async.cg.shared.global [%0], [%1], 16;"
                :: "r"(dst + n * 144 + ch * 16), "l"(src + (size_t)n * KTOT + ch * 8));
        }
        asm volatile("cp.async.commit_group;" ::: "memory");
    }

    // Stage idx PERMUTED: byte for local token t of book c goes to
    //   s_idx[c*128 + (t>>5)*32 + (t&7)*4 + ((t&31)>>3)]
    {
        unsigned char* si = smem + SM_IDX;
        for (int i = tid; i < 1024; i += 256) {
            int c = i >> 3, t0 = (i & 7) * 16;
            uint4 v = *(const uint4*)(g_idxT + ((size_t)c << 12) + m0 + t0);
            const unsigned char* vb = (const unsigned char*)&v;
            int strip = t0 >> 5;
#pragma unroll
            for (int j = 0; j < 16; ++j) {
                int tw = (t0 & 31) + j;
                si[c * 128 + strip * 32 + (tw & 7) * 4 + (tw >> 3)] = vb[j];
            }
        }
        float* sbias = (float*)(smem + SM_BIAS);
        if (tid < 128) sbias[tid] = bias[o0 + tid];
    }
    __syncthreads();

    float acc[2][8][4];
#pragma unroll
    for (int mf = 0; mf < 2; ++mf)
#pragma unroll
        for (int nf = 0; nf < 8; ++nf)
#pragma unroll
            for (int q = 0; q < 4; ++q) acc[mf][nf][q] = 0.0f;

    const uint32_t c0    = (uint32_t)((lane & 3) * 2);
    const uint32_t xmask = c0 * 0x01010101u;
    const uint32_t lmb   = (uint32_t)((lane & 7) * 144 + (lane >> 3) * 16);
    const unsigned char* s_idx = smem + SM_IDX;
    const uint32_t ioff  = (uint32_t)(ms * 32 + (lane >> 2) * 4);

    for (int s = 0; s < 32; ++s) {
        asm volatile("cp.async.wait_group 1;" ::: "memory");
        GBAR(gbar);   // group's half of stage s ready; iter s-1 reads complete
        uint32_t bufB = sb + SM_B + (s % 3) * BSTG;
#pragma unroll
        for (int cb = 0; cb < 4; ++cb) {
            int c = s * 4 + cb;
            uint32_t p  = *(const uint32_t*)(s_idx + (c << 7) + ioff);
            uint32_t tp = p ^ xmask;
            uint32_t s0 = (tp & 0xFu) << 4;
            uint32_t s1 = ((tp >> 8) & 0xFu) << 4;
            uint32_t s2 = ((tp >> 16) & 0xFu) << 4;
            uint32_t s3 = (tp >> 24) << 4;
            uint32_t a00 = shl_oh(s0),        a01 = shl_oh(s1);
            uint32_t a02 = shl_oh(s0 ^ 128u), a03 = shl_oh(s1 ^ 128u);
            uint32_t a10 = shl_oh(s2),        a11 = shl_oh(s3);
            uint32_t a12 = shl_oh(s2 ^ 128u), a13 = shl_oh(s3 ^ 128u);
            uint32_t kb = bufB + (uint32_t)(cb * 32) + (uint32_t)(ns * 64 * 144) + lmb;
#pragma unroll
            for (int nf = 0; nf < 8; ++nf) {
                uint32_t b0, b1;
                asm volatile("ldmatrix.sync.aligned.m8n8.x2.shared.b16 {%0,%1}, [%2];"
                             : "=r"(b0), "=r"(b1) : "r"(kb + (uint32_t)(nf * 8 * 144)));
                MMA(acc[0][nf], a00, a01, a02, a03, b0, b1);
                MMA(acc[1][nf], a10, a11, a12, a13, b0, b1);
            }
        }
        // Issue stage s+2 into ring slot (s+2)%3 == (s-1)%3 (consumed at s-1,
        // ordered by this iteration's GBAR).
        if (s + 2 < 32) {
            uint32_t dst = sb + SM_B + ((s + 2) % 3) * BSTG;
            const __half* src = gB + (s + 2) * 64;
#pragma unroll
            for (int r = 0; r < 4; ++r) {
                int i = gtid + r * 128, n = ns * 64 + (i >> 3), ch = i & 7;
                asm volatile("cp.async.cg.shared.global [%0], [%1], 16;"
                    :: "r"(dst + n * 144 + ch * 16), "l"(src + (size_t)n * KTOT + ch * 8));
            }
        }
        asm volatile("cp.async.commit_group;" ::: "memory");
    }

    // Epilogue: add bias, store
    const float* sbias = (const float*)(smem + SM_BIAS);
#pragma unroll
    for (int mf = 0; mf < 2; ++mf) {
        int row = m0 + ms * 32 + mf * 16 + (lane >> 2);
#pragma unroll
        for (int nf = 0; nf < 8; ++nf) {
            int colL = ns * 64 + nf * 8 + (int)c0;
            float2 bv = *(const float2*)(sbias + colL);
            float2 v0 = make_float2(acc[mf][nf][0] + bv.x, acc[mf][nf][1] + bv.y);
            float2 v1 = make_float2(acc[mf][nf][2] + bv.x, acc[mf][nf][3] + bv.y);
            *(float2*)(out + (size_t)row * OUT_DIM + o0 + colL) = v0;
            *(float2*)(out + (size_t)(row + 8) * OUT_DIM + o0 + colL) = v1;
        }
    }
}

// ---------------------------------------------------------------------------
extern "C" void kernel_launch(void* const* d_in, const int* in_sizes, int n_in,
                              void* d_out, int out_size)
{
    const float* x     = (const float*)d_in[0];
    const float* wgt   = (const float*)d_in[1];
    const float* cents = (const float*)d_in[2];
    const float* bias  = (const float*)d_in[3];
    float*       out   = (float*)d_out;

    cudaFuncSetAttribute(onehot_hmma_kernel,
                         cudaFuncAttributeMaxDynamicSharedMemorySize, SM_TOT);

    prologue_kernel<<<2560, 256>>>(x, wgt, cents);
    onehot_hmma_kernel<<<dim3(OUT_DIM / 128, N_TOK / 128), 256, SM_TOT>>>(bias, out);
}